// round 3
// baseline (speedup 1.0000x reference)
#include <cuda_runtime.h>
#include <math.h>
#include <stdint.h>

#define BDIM 4
#define SEQ 1024
#define DMODEL 1024
#define NH 16
#define DH 64
#define SPAN 256
#define TWOSPAN 512
#define NBATCH (BDIM*NH)   /* 64 */

// ---------------- scratch (device globals; no allocation allowed) ----------
__device__ float g_q   [(size_t)NBATCH * SEQ * DH];        // [z][s][d]
__device__ float g_k   [(size_t)NBATCH * SEQ * DH];        // [z][s][d]
__device__ float g_vt  [(size_t)NBATCH * DH * SEQ];        // [z][d][s]  (transposed V)
__device__ float g_posk[(size_t)NH * TWOSPAN * DH];        // [h][p][d]
__device__ float g_posq[(size_t)NH * TWOSPAN * DH];
__device__ float g_c2p [(size_t)NBATCH * SEQ * TWOSPAN];   // [z][q][p] (pre-scaled)
__device__ float g_p2c [(size_t)NBATCH * SEQ * TWOSPAN];   // [z][k][p] (pre-scaled)
__device__ float g_sc  [(size_t)NBATCH * SEQ * SEQ];       // [z][q][k]
__device__ float g_ctx [(size_t)BDIM * SEQ * DMODEL];
__device__ int   g_lut [2047];                              // clipped bucket idx per delta

// ================= small helpers ============================================
__device__ __forceinline__ uint32_t cvt_tf32(float x) {
    uint32_t r;
    asm("cvt.rna.tf32.f32 %0, %1;" : "=r"(r) : "f"(x));
    return r;
}
#define MMA_TF32(d, a, b) \
    asm volatile("mma.sync.aligned.m16n8k8.row.col.f32.tf32.tf32.f32 " \
        "{%0,%1,%2,%3}, {%4,%5,%6,%7}, {%8,%9}, {%0,%1,%2,%3};" \
        : "+f"((d)[0]), "+f"((d)[1]), "+f"((d)[2]), "+f"((d)[3]) \
        : "r"((a)[0]), "r"((a)[1]), "r"((a)[2]), "r"((a)[3]), \
          "r"((b)[0]), "r"((b)[1]))

// ================= rel-position bucket LUT ==================================
__device__ __forceinline__ int rel_bucket(int rel) {
    float abs_pos = (rel < 128 && rel > -128) ? 127.0f : fabsf((float)rel);
    if (abs_pos <= 128.0f) return rel;
    float sgn = (rel > 0) ? 1.0f : -1.0f;
    float log_pos = ceilf(logf(abs_pos * (1.0f/128.0f)) / logf(511.0f/128.0f) * 127.0f) + 128.0f;
    return (int)(log_pos * sgn);
}
__global__ void lut_k() {
    int t = blockIdx.x * blockDim.x + threadIdx.x;
    if (t >= 2047) return;
    int b = rel_bucket(t - 1023);
    g_lut[t] = min(max(b + SPAN, 0), TWOSPAN - 1);
}

// ================= unified tf32 mma.sync GEMM (C = A @ B^T + epilogues) =====
#define EPI_HEADS   0
#define EPI_HEADS_T 1
#define EPI_POS     2
#define EPI_SCALE   3
#define EPI_SCORE   4
#define EPI_CTX     5
#define EPI_OUT     6

template<int EPI, int BN, int CH>
__global__ void __launch_bounds__(256)
tc_gemm(const float* __restrict__ A, const float* __restrict__ Bm,
        const float* __restrict__ bias, const float* __restrict__ ex1,
        const float* __restrict__ ex2, float* __restrict__ C,
        int Ka, size_t sA, size_t sB, int nbMod, float alpha)
{
    constexpr int WN    = BN / 4;      // warp N tile (32 or 16)
    constexpr int NF    = WN / 8;      // n8 fragments per warp (4 or 2)
    constexpr int BNW   = BN / 32;     // B float4-load iterations
    constexpr int AELEM = 128 * 32;    // elements per A stage
    constexpr int BELEM = BN * 32;

    extern __shared__ uint32_t smem_u[];
    uint32_t* As = smem_u;                   // 2 stages of A (tf32 bits)
    uint32_t* Bs = smem_u + 2 * AELEM;       // 2 stages of B

    const int tid  = threadIdx.x;
    const int lane = tid & 31, wid = tid >> 5;
    const int wr = wid & 1, wc = wid >> 1;   // 2 x 4 warp grid
    const int rq = lane >> 2, cc = lane & 3;
    const int z  = blockIdx.z;
    const int m0 = blockIdx.y * 128;
    const int n0 = blockIdx.x * BN;

    A  += (size_t)z * sA + (size_t)m0 * Ka;
    Bm += (size_t)(nbMod ? (z % nbMod) : 0) * sB + (size_t)n0 * Ka;

    float acc[4][NF][4];
    #pragma unroll
    for (int a = 0; a < 4; a++)
        #pragma unroll
        for (int b = 0; b < NF; b++)
            #pragma unroll
            for (int c = 0; c < 4; c++) acc[a][b][c] = 0.0f;

    // fragment element-base offsets (row*32 + cc); row&7 == rq for all frags
    int aBase[4][2];
    #pragma unroll
    for (int mi = 0; mi < 4; mi++) {
        int r = wr * 64 + mi * 16 + rq;
        aBase[mi][0] = r * 32 + cc;
        aBase[mi][1] = (r + 8) * 32 + cc;
    }
    int bBase[NF];
    #pragma unroll
    for (int ni = 0; ni < NF; ni++)
        bBase[ni] = (wc * WN + ni * 8 + rq) * 32 + cc;

    uint4 pa[4], pb[BNW];

    auto ldgAB = [&](int k0) {
        #pragma unroll
        for (int j = 0; j < 4; j++) {
            int idx = j * 256 + tid, row = idx >> 3, kg = idx & 7;
            float4 v = *(const float4*)(A + (size_t)row * Ka + k0 + kg * 4);
            pa[j] = make_uint4(cvt_tf32(v.x), cvt_tf32(v.y), cvt_tf32(v.z), cvt_tf32(v.w));
        }
        #pragma unroll
        for (int j = 0; j < BNW; j++) {
            int idx = j * 256 + tid, row = idx >> 3, kg = idx & 7;
            float4 v = *(const float4*)(Bm + (size_t)row * Ka + k0 + kg * 4);
            pb[j] = make_uint4(cvt_tf32(v.x), cvt_tf32(v.y), cvt_tf32(v.z), cvt_tf32(v.w));
        }
    };
    auto stsAB = [&](int s) {
        #pragma unroll
        for (int j = 0; j < 4; j++) {
            int idx = j * 256 + tid, row = idx >> 3, kg = idx & 7;
            *(uint4*)&As[s * AELEM + row * 32 + ((kg ^ (row & 7)) << 2)] = pa[j];
        }
        #pragma unroll
        for (int j = 0; j < BNW; j++) {
            int idx = j * 256 + tid, row = idx >> 3, kg = idx & 7;
            *(uint4*)&Bs[s * BELEM + row * 32 + ((kg ^ (row & 7)) << 2)] = pb[j];
        }
    };

    ldgAB(0);
    stsAB(0);
    #pragma unroll 1
    for (int i = 0; i < CH; i++) {
        const int s = i & 1;
        if (i + 1 < CH) ldgAB((i + 1) * 32);
        __syncthreads();
        const uint32_t* as = As + s * AELEM;
        const uint32_t* bs = Bs + s * BELEM;
        #pragma unroll
        for (int ks = 0; ks < 4; ks++) {
            const int o0 = ((2 * ks) ^ rq) << 2;
            const int o1 = ((2 * ks + 1) ^ rq) << 2;
            uint32_t af[4][4];
            #pragma unroll
            for (int mi = 0; mi < 4; mi++) {
                af[mi][0] = as[aBase[mi][0] + o0];
                af[mi][1] = as[aBase[mi][1] + o0];
                af[mi][2] = as[aBase[mi][0] + o1];
                af[mi][3] = as[aBase[mi][1] + o1];
            }
            uint32_t bf[NF][2];
            #pragma unroll
            for (int ni = 0; ni < NF; ni++) {
                bf[ni][0] = bs[bBase[ni] + o0];
                bf[ni][1] = bs[bBase[ni] + o1];
            }
            #pragma unroll
            for (int mi = 0; mi < 4; mi++)
                #pragma unroll
                for (int ni = 0; ni < NF; ni++)
                    MMA_TF32(acc[mi][ni], af[mi], bf[ni]);
        }
        __syncthreads();
        if (i + 1 < CH) stsAB((i + 1) & 1);
    }

    // ---------------- epilogue: frags -> smem stage -> global ----------------
    float* stage = (float*)smem_u;                 // 128 x 33 fp32 (A region)
    float* p2s   = (float*)(smem_u + 2 * AELEM);   // SCORE gather staging (B region)

    #pragma unroll 1
    for (int cb = 0; cb < BN / 32; cb++) {
        const int n0c = n0 + cb * 32;
        int iLo = 0;
        if (EPI == EPI_SCORE) {
            int dLo = min(max(n0c - m0 - 127 + 1023, 0), 2046);
            iLo = g_lut[dLo];
            const float* p2cz = ex2 + (size_t)z * SEQ * TWOSPAN;
            #pragma unroll 1
            for (int e = tid; e < 32 * 160; e += 256) {
                int rn = e / 160, col = e - rn * 160;
                int ix = min(iLo + col, TWOSPAN - 1);
                p2s[rn * 160 + col] = p2cz[(size_t)(n0c + rn) * TWOSPAN + ix];
            }
        }
        // write this 32-col block's fragments into stage
        #pragma unroll
        for (int mi = 0; mi < 4; mi++)
            #pragma unroll
            for (int ni = 0; ni < NF; ni++) {
                int gc = wc * WN + ni * 8 + 2 * cc;
                if ((gc >> 5) == cb) {
                    int sc2 = gc & 31;
                    int r0 = wr * 64 + mi * 16 + rq;
                    stage[r0 * 33 + sc2]           = acc[mi][ni][0];
                    stage[r0 * 33 + sc2 + 1]       = acc[mi][ni][1];
                    stage[(r0 + 8) * 33 + sc2]     = acc[mi][ni][2];
                    stage[(r0 + 8) * 33 + sc2 + 1] = acc[mi][ni][3];
                }
            }
        __syncthreads();

        if (EPI == EPI_HEADS_T) {
            // column-major traversal: coalesced transposed store
            #pragma unroll 1
            for (int j = 0; j < 16; j++) {
                int e = j * 256 + tid;
                int row = e & 127, c = e >> 7;
                int m = m0 + row, n = n0c + c;
                float val = stage[row * 33 + c] + bias[n];
                int b = m >> 10, sq = m & 1023;
                int zz = b * NH + (n >> 6), dd = n & 63;
                C[((size_t)zz * DH + dd) * SEQ + sq] = val;
            }
        } else {
            #pragma unroll 1
            for (int j = 0; j < 16; j++) {
                int e = j * 256 + tid;
                int row = e >> 5, c = e & 31;
                int m = m0 + row, n = n0c + c;
                float val = stage[row * 33 + c];
                if (EPI == EPI_HEADS) {
                    val += bias[n];
                    int b = m >> 10, sq = m & 1023, h = n >> 6, dd = n & 63;
                    C[(((size_t)(b * NH + h)) * SEQ + sq) * DH + dd] = val;
                } else if (EPI == EPI_POS) {
                    val += bias[n];
                    int h = n >> 6, dd = n & 63;
                    C[((size_t)h * TWOSPAN + m) * DH + dd] = val;
                } else if (EPI == EPI_SCALE) {
                    C[(size_t)z * SEQ * TWOSPAN + (size_t)m * TWOSPAN + n] = val * alpha;
                } else if (EPI == EPI_SCORE) {
                    const float* c2pz = ex1 + (size_t)z * SEQ * TWOSPAN;
                    int idx1 = g_lut[m - n + 1023];
                    int idx2 = g_lut[n - m + 1023];
                    val = val * alpha + c2pz[(size_t)m * TWOSPAN + idx1]
                                      + p2s[c * 160 + (idx2 - iLo)];
                    C[(size_t)z * SEQ * SEQ + (size_t)m * SEQ + n] = val;
                } else if (EPI == EPI_CTX) {
                    int b = z >> 4, h = z & 15;
                    C[((size_t)b * SEQ + m) * DMODEL + h * DH + n] = val;
                } else { // EPI_OUT
                    val += bias[n] + ex1[(size_t)m * DMODEL + n];
                    C[(size_t)m * DMODEL + n] = val;
                }
            }
        }
        __syncthreads();
    }
}

// ================= softmax & layernorm (SIMT, mem-bound) ====================
__device__ __forceinline__ float block_sum(float v, float* sh) {
    #pragma unroll
    for (int o = 16; o; o >>= 1) v += __shfl_xor_sync(0xffffffffu, v, o);
    int lane = threadIdx.x & 31, w = threadIdx.x >> 5;
    __syncthreads();
    if (lane == 0) sh[w] = v;
    __syncthreads();
    if (w == 0) {
        float x = (lane < (blockDim.x >> 5)) ? sh[lane] : 0.0f;
        #pragma unroll
        for (int o = 16; o; o >>= 1) x += __shfl_xor_sync(0xffffffffu, x, o);
        if (lane == 0) sh[0] = x;
    }
    __syncthreads();
    return sh[0];
}
__device__ __forceinline__ float block_max(float v, float* sh) {
    #pragma unroll
    for (int o = 16; o; o >>= 1) v = fmaxf(v, __shfl_xor_sync(0xffffffffu, v, o));
    int lane = threadIdx.x & 31, w = threadIdx.x >> 5;
    __syncthreads();
    if (lane == 0) sh[w] = v;
    __syncthreads();
    if (w == 0) {
        float x = (lane < (blockDim.x >> 5)) ? sh[lane] : -INFINITY;
        #pragma unroll
        for (int o = 16; o; o >>= 1) x = fmaxf(x, __shfl_xor_sync(0xffffffffu, x, o));
        if (lane == 0) sh[0] = x;
    }
    __syncthreads();
    return sh[0];
}
__global__ void softmax_k(float* __restrict__ Sc, const int* __restrict__ mask) {
    __shared__ float sh[32];
    int row = blockIdx.x;
    int b = row >> 14;
    int i = row & 1023;
    float* p = Sc + (size_t)row * SEQ;
    const int* mrow = mask + ((size_t)b << 20) + ((size_t)i << 10);
    int t = threadIdx.x;
    float4 v = *(const float4*)(p + t * 4);
    int4 mm = *(const int4*)(mrow + t * 4);
    const float NEG = -3.402823466e38f;
    float x0 = mm.x ? v.x : NEG, x1 = mm.y ? v.y : NEG;
    float x2 = mm.z ? v.z : NEG, x3 = mm.w ? v.w : NEG;
    float mx = block_max(fmaxf(fmaxf(x0, x1), fmaxf(x2, x3)), sh);
    float e0 = expf(x0 - mx), e1 = expf(x1 - mx), e2 = expf(x2 - mx), e3 = expf(x3 - mx);
    float s = block_sum(e0 + e1 + e2 + e3, sh);
    float inv = 1.0f / s;
    float4 o;
    o.x = mm.x ? e0 * inv : 0.0f; o.y = mm.y ? e1 * inv : 0.0f;
    o.z = mm.z ? e2 * inv : 0.0f; o.w = mm.w ? e3 * inv : 0.0f;
    *(float4*)(p + t * 4) = o;
}
__global__ void ln_k(float* __restrict__ out, const float* __restrict__ gamma,
                     const float* __restrict__ beta) {
    __shared__ float sh[32];
    int row = blockIdx.x, t = threadIdx.x;
    float* p = out + (size_t)row * DMODEL;
    float4 v = *(const float4*)(p + t * 4);
    float mean = block_sum(v.x + v.y + v.z + v.w, sh) * (1.0f / DMODEL);
    float dx = v.x - mean, dy = v.y - mean, dz = v.z - mean, dw = v.w - mean;
    float var = block_sum(dx*dx + dy*dy + dz*dz + dw*dw, sh) * (1.0f / DMODEL);
    float inv = rsqrtf(var + 1e-7f);
    float4 g = *(const float4*)(gamma + t * 4);
    float4 bb = *(const float4*)(beta + t * 4);
    float4 o;
    o.x = dx*inv*g.x + bb.x; o.y = dy*inv*g.y + bb.y;
    o.z = dz*inv*g.z + bb.z; o.w = dw*inv*g.w + bb.w;
    *(float4*)(p + t * 4) = o;
}

// ================= launch ====================================================
extern "C" void kernel_launch(void* const* d_in, const int* in_sizes, int n_in,
                              void* d_out, int out_size) {
    const float* hidden = (const float*)d_in[0];
    const int*   mask   = (const int*)  d_in[1];
    const float* rel    = (const float*)d_in[2];
    const float* Wq     = (const float*)d_in[3];
    const float* bq     = (const float*)d_in[4];
    const float* Wk     = (const float*)d_in[5];
    const float* bk     = (const float*)d_in[6];
    const float* Wv     = (const float*)d_in[7];
    const float* bv     = (const float*)d_in[8];
    const float* Wo     = (const float*)d_in[9];
    const float* bo     = (const float*)d_in[10];
    const float* gamma  = (const float*)d_in[11];
    const float* beta   = (const float*)d_in[12];
    float* out = (float*)d_out;

    float *q, *k, *vt, *pk, *pq, *c2p, *p2c, *sc, *ctx;
    cudaGetSymbolAddress((void**)&q,   g_q);
    cudaGetSymbolAddress((void**)&k,   g_k);
    cudaGetSymbolAddress((void**)&vt,  g_vt);
    cudaGetSymbolAddress((void**)&pk,  g_posk);
    cudaGetSymbolAddress((void**)&pq,  g_posq);
    cudaGetSymbolAddress((void**)&c2p, g_c2p);
    cudaGetSymbolAddress((void**)&p2c, g_p2c);
    cudaGetSymbolAddress((void**)&sc,  g_sc);
    cudaGetSymbolAddress((void**)&ctx, g_ctx);

    const float alpha = 1.0f / sqrtf((float)(DH * 3));
    const size_t SM128 = (size_t)(2 * 128 * 32 + 2 * 128 * 32) * 4;   // 65536
    const size_t SM64  = (size_t)(2 * 128 * 32 + 2 * 64 * 32) * 4;    // 49152

    cudaFuncSetAttribute((const void*)tc_gemm<EPI_HEADS,  128, 32>, cudaFuncAttributeMaxDynamicSharedMemorySize, (int)SM128);
    cudaFuncSetAttribute((const void*)tc_gemm<EPI_HEADS_T,128, 32>, cudaFuncAttributeMaxDynamicSharedMemorySize, (int)SM128);
    cudaFuncSetAttribute((const void*)tc_gemm<EPI_POS,    128, 32>, cudaFuncAttributeMaxDynamicSharedMemorySize, (int)SM128);
    cudaFuncSetAttribute((const void*)tc_gemm<EPI_SCALE,  128,  2>, cudaFuncAttributeMaxDynamicSharedMemorySize, (int)SM128);
    cudaFuncSetAttribute((const void*)tc_gemm<EPI_SCORE,  128,  2>, cudaFuncAttributeMaxDynamicSharedMemorySize, (int)SM128);
    cudaFuncSetAttribute((const void*)tc_gemm<EPI_CTX,     64, 32>, cudaFuncAttributeMaxDynamicSharedMemorySize, (int)SM64);
    cudaFuncSetAttribute((const void*)tc_gemm<EPI_OUT,    128, 32>, cudaFuncAttributeMaxDynamicSharedMemorySize, (int)SM128);

    lut_k<<<2, 1024>>>();

    // Q, K, V projections (M=4096, N=1024, K=1024)
    tc_gemm<EPI_HEADS,  128, 32><<<dim3(8, 32, 1), 256, SM128>>>(hidden, Wq, bq, 0, 0, q,  1024, 0, 0, 0, 1.f);
    tc_gemm<EPI_HEADS,  128, 32><<<dim3(8, 32, 1), 256, SM128>>>(hidden, Wk, bk, 0, 0, k,  1024, 0, 0, 0, 1.f);
    tc_gemm<EPI_HEADS_T,128, 32><<<dim3(8, 32, 1), 256, SM128>>>(hidden, Wv, bv, 0, 0, vt, 1024, 0, 0, 0, 1.f);
    // position projections (M=512)
    tc_gemm<EPI_POS, 128, 32><<<dim3(8, 4, 1), 256, SM128>>>(rel, Wk, bk, 0, 0, pk, 1024, 0, 0, 0, 1.f);
    tc_gemm<EPI_POS, 128, 32><<<dim3(8, 4, 1), 256, SM128>>>(rel, Wq, bq, 0, 0, pq, 1024, 0, 0, 0, 1.f);
    // c2p / p2c attention tables (pre-scaled by alpha), per-z batched, K=64
    tc_gemm<EPI_SCALE, 128, 2><<<dim3(4, 8, NBATCH), 256, SM128>>>(q, pk, 0, 0, 0, c2p, 64, (size_t)SEQ*DH, (size_t)TWOSPAN*DH, NH, alpha);
    tc_gemm<EPI_SCALE, 128, 2><<<dim3(4, 8, NBATCH), 256, SM128>>>(k, pq, 0, 0, 0, p2c, 64, (size_t)SEQ*DH, (size_t)TWOSPAN*DH, NH, alpha);
    // scores = alpha*QK^T + c2p/p2c gathers
    tc_gemm<EPI_SCORE, 128, 2><<<dim3(8, 8, NBATCH), 256, SM128>>>(q, k, 0, c2p, p2c, sc, 64, (size_t)SEQ*DH, (size_t)SEQ*DH, NBATCH, alpha);

    softmax_k<<<NBATCH * SEQ, 256>>>(sc, mask);

    // ctx = P @ V   (A = probs [S,S] K-major, B = vt [64, S] K-major)
    tc_gemm<EPI_CTX, 64, 32><<<dim3(1, 8, NBATCH), 256, SM64>>>(sc, vt, 0, 0, 0, ctx, 1024, (size_t)SEQ*SEQ, (size_t)DH*SEQ, NBATCH, 1.f);
    // output projection + residual
    tc_gemm<EPI_OUT, 128, 32><<<dim3(8, 32, 1), 256, SM128>>>(ctx, Wo, bo, hidden, 0, out, 1024, 0, 0, 0, 1.f);

    ln_k<<<BDIM * SEQ, 256>>>(out, gamma, beta);
}

// round 4
// speedup vs baseline: 1.7315x; 1.7315x over previous
#include <cuda_runtime.h>
#include <math.h>
#include <stdint.h>

#define BDIM 4
#define SEQ 1024
#define DMODEL 1024
#define NH 16
#define DH 64
#define SPAN 256
#define TWOSPAN 512
#define NBATCH (BDIM*NH)   /* 64 */

// ---------------- scratch (device globals; no allocation allowed) ----------
__device__ float g_q   [(size_t)NBATCH * SEQ * DH];        // [z][s][d]
__device__ float g_k   [(size_t)NBATCH * SEQ * DH];        // [z][s][d]
__device__ float g_vt  [(size_t)NBATCH * DH * SEQ];        // [z][d][s]  (transposed V)
__device__ float g_posk[(size_t)NH * TWOSPAN * DH];        // [h][p][d]
__device__ float g_posq[(size_t)NH * TWOSPAN * DH];
__device__ float g_c2p [(size_t)NBATCH * SEQ * TWOSPAN];   // [z][q][p] (pre-scaled)
__device__ float g_p2c [(size_t)NBATCH * SEQ * TWOSPAN];   // [z][k][p] (pre-scaled)
__device__ float g_sc  [(size_t)NBATCH * SEQ * SEQ];       // [z][q][k]
__device__ float g_ctx [(size_t)BDIM * SEQ * DMODEL];
__device__ int   g_lut [2047];                              // clipped bucket idx per delta

// ================= small helpers ============================================
#define MMA_TF32(d, a, b) \
    asm volatile("mma.sync.aligned.m16n8k8.row.col.f32.tf32.tf32.f32 " \
        "{%0,%1,%2,%3}, {%4,%5,%6,%7}, {%8,%9}, {%0,%1,%2,%3};" \
        : "+f"((d)[0]), "+f"((d)[1]), "+f"((d)[2]), "+f"((d)[3]) \
        : "r"((a)[0]), "r"((a)[1]), "r"((a)[2]), "r"((a)[3]), \
          "r"((b)[0]), "r"((b)[1]))

__device__ __forceinline__ void cp16(uint32_t dst, const void* src) {
    asm volatile("cp.async.cg.shared.global [%0], [%1], 16;" :: "r"(dst), "l"(src));
}
#define CP_COMMIT() asm volatile("cp.async.commit_group;" ::: "memory")
#define CP_WAIT(n)  asm volatile("cp.async.wait_group %0;" :: "n"(n) : "memory")

// ================= rel-position bucket LUT ==================================
__device__ __forceinline__ int rel_bucket(int rel) {
    float abs_pos = (rel < 128 && rel > -128) ? 127.0f : fabsf((float)rel);
    if (abs_pos <= 128.0f) return rel;
    float sgn = (rel > 0) ? 1.0f : -1.0f;
    float log_pos = ceilf(logf(abs_pos * (1.0f/128.0f)) / logf(511.0f/128.0f) * 127.0f) + 128.0f;
    return (int)(log_pos * sgn);
}
__global__ void lut_k() {
    int t = blockIdx.x * blockDim.x + threadIdx.x;
    if (t >= 2047) return;
    int b = rel_bucket(t - 1023);
    g_lut[t] = min(max(b + SPAN, 0), TWOSPAN - 1);
}

// ================= unified tf32 mma.sync GEMM (C = A @ B^T + epilogues) =====
#define EPI_HEADS   0
#define EPI_HEADS_T 1
#define EPI_POS     2
#define EPI_SCALE   3
#define EPI_SCORE   4
#define EPI_CTX     5
#define EPI_OUT     6

template<int EPI, int BN, int CH>
__global__ void __launch_bounds__(256, 2)
tc_gemm(const float* __restrict__ A, const float* __restrict__ Bm,
        const float* __restrict__ bias, const float* __restrict__ ex1,
        const float* __restrict__ ex2, float* __restrict__ C,
        int Ka, size_t sA, size_t sB, int nbMod, float alpha)
{
    constexpr int NS    = 3;           // cp.async pipeline stages
    constexpr int WN    = BN / 4;      // warp N tile (32 or 16)
    constexpr int NF    = WN / 8;      // n8 fragments per warp (4 or 2)
    constexpr int BNW   = BN / 32;     // B cp.async iterations
    constexpr int AELEM = 128 * 32;    // elements per A stage
    constexpr int BELEM = BN * 32;

    extern __shared__ uint32_t smem_u[];
    const uint32_t smemU = (uint32_t)__cvta_generic_to_shared(smem_u);

    const int tid  = threadIdx.x;
    const int lane = tid & 31, wid = tid >> 5;
    const int wr = wid & 1, wc = wid >> 1;   // 2 x 4 warp grid
    const int rq = lane >> 2, cc = lane & 3;
    const int z  = blockIdx.z;
    const int m0 = blockIdx.y * 128;
    const int n0 = blockIdx.x * BN;

    A  += (size_t)z * sA + (size_t)m0 * Ka;
    Bm += (size_t)(nbMod ? (z % nbMod) : 0) * sB + (size_t)n0 * Ka;

    float acc[4][NF][4];
    #pragma unroll
    for (int a = 0; a < 4; a++)
        #pragma unroll
        for (int b = 0; b < NF; b++)
            #pragma unroll
            for (int c = 0; c < 4; c++) acc[a][b][c] = 0.0f;

    // fragment element-base offsets (row*32 + cc); row&7 == rq for all frags
    int aBase[4][2];
    #pragma unroll
    for (int mi = 0; mi < 4; mi++) {
        int r = wr * 64 + mi * 16 + rq;
        aBase[mi][0] = r * 32 + cc;
        aBase[mi][1] = (r + 8) * 32 + cc;
    }
    int bBase[NF];
    #pragma unroll
    for (int ni = 0; ni < NF; ni++)
        bBase[ni] = (wc * WN + ni * 8 + rq) * 32 + cc;

    // per-thread cp.async coordinates
    const int crow = tid >> 3;          // 0..31 (A: +j*32 rows), row within group
    const int ckg  = tid & 7;           // k-group of 4 floats

    auto issue = [&](int chunk) {
        const int s  = chunk % NS;
        const int k0 = chunk * 32;
        #pragma unroll
        for (int j = 0; j < 4; j++) {
            int row = j * 32 + crow;
            uint32_t dst = smemU + (uint32_t)(s * AELEM + row * 32 + ((ckg ^ (row & 7)) << 2)) * 4u;
            cp16(dst, A + (size_t)row * Ka + k0 + ckg * 4);
        }
        #pragma unroll
        for (int j = 0; j < BNW; j++) {
            int row = j * 32 + crow;
            uint32_t dst = smemU + (uint32_t)(NS * AELEM + s * BELEM + row * 32 + ((ckg ^ (row & 7)) << 2)) * 4u;
            cp16(dst, Bm + (size_t)row * Ka + k0 + ckg * 4);
        }
    };

    #pragma unroll
    for (int c = 0; c < NS - 1; c++) {
        if (c < CH) issue(c);
        CP_COMMIT();
    }

    #pragma unroll 1
    for (int i = 0; i < CH; i++) {
        CP_WAIT(NS - 2);
        __syncthreads();
        if (i + NS - 1 < CH) issue(i + NS - 1);
        CP_COMMIT();

        const uint32_t* as = smem_u + (i % NS) * AELEM;
        const uint32_t* bs = smem_u + NS * AELEM + (i % NS) * BELEM;
        #pragma unroll
        for (int ks = 0; ks < 4; ks++) {
            const int o0 = ((2 * ks) ^ rq) << 2;
            const int o1 = ((2 * ks + 1) ^ rq) << 2;
            uint32_t af[4][4];
            #pragma unroll
            for (int mi = 0; mi < 4; mi++) {
                af[mi][0] = as[aBase[mi][0] + o0];
                af[mi][1] = as[aBase[mi][1] + o0];
                af[mi][2] = as[aBase[mi][0] + o1];
                af[mi][3] = as[aBase[mi][1] + o1];
            }
            uint32_t bf[NF][2];
            #pragma unroll
            for (int ni = 0; ni < NF; ni++) {
                bf[ni][0] = bs[bBase[ni] + o0];
                bf[ni][1] = bs[bBase[ni] + o1];
            }
            #pragma unroll
            for (int mi = 0; mi < 4; mi++)
                #pragma unroll
                for (int ni = 0; ni < NF; ni++)
                    MMA_TF32(acc[mi][ni], af[mi], bf[ni]);
        }
    }
    CP_WAIT(0);
    __syncthreads();

    // ---------------- epilogue: frags -> smem stage -> global ----------------
    float* stage = (float*)smem_u;                 // 128 x 33 fp32 (A region)
    float* p2s   = (float*)(smem_u + NS * AELEM);  // SCORE gather staging (B region)

    #pragma unroll 1
    for (int cb = 0; cb < BN / 32; cb++) {
        const int n0c = n0 + cb * 32;
        int iLo = 0;
        if (EPI == EPI_SCORE) {
            int dLo = min(max(n0c - m0 - 127 + 1023, 0), 2046);
            iLo = g_lut[dLo];
            const float* p2cz = ex2 + (size_t)z * SEQ * TWOSPAN;
            #pragma unroll 1
            for (int e = tid; e < 32 * 160; e += 256) {
                int rn = e / 160, col = e - rn * 160;
                int ix = min(iLo + col, TWOSPAN - 1);
                p2s[rn * 160 + col] = p2cz[(size_t)(n0c + rn) * TWOSPAN + ix];
            }
        }
        // write this 32-col block's fragments into stage
        #pragma unroll
        for (int mi = 0; mi < 4; mi++)
            #pragma unroll
            for (int ni = 0; ni < NF; ni++) {
                int gc = wc * WN + ni * 8 + 2 * cc;
                if ((gc >> 5) == cb) {
                    int sc2 = gc & 31;
                    int r0 = wr * 64 + mi * 16 + rq;
                    stage[r0 * 33 + sc2]           = acc[mi][ni][0];
                    stage[r0 * 33 + sc2 + 1]       = acc[mi][ni][1];
                    stage[(r0 + 8) * 33 + sc2]     = acc[mi][ni][2];
                    stage[(r0 + 8) * 33 + sc2 + 1] = acc[mi][ni][3];
                }
            }
        __syncthreads();

        if (EPI == EPI_HEADS_T) {
            // column-major traversal: coalesced transposed store
            #pragma unroll 1
            for (int j = 0; j < 16; j++) {
                int e = j * 256 + tid;
                int row = e & 127, c = e >> 7;
                int m = m0 + row, n = n0c + c;
                float val = stage[row * 33 + c] + bias[n];
                int b = m >> 10, sq = m & 1023;
                int zz = b * NH + (n >> 6), dd = n & 63;
                C[((size_t)zz * DH + dd) * SEQ + sq] = val;
            }
        } else {
            #pragma unroll 1
            for (int j = 0; j < 16; j++) {
                int e = j * 256 + tid;
                int row = e >> 5, c = e & 31;
                int m = m0 + row, n = n0c + c;
                float val = stage[row * 33 + c];
                if (EPI == EPI_HEADS) {
                    val += bias[n];
                    int b = m >> 10, sq = m & 1023, h = n >> 6, dd = n & 63;
                    C[(((size_t)(b * NH + h)) * SEQ + sq) * DH + dd] = val;
                } else if (EPI == EPI_POS) {
                    val += bias[n];
                    int h = n >> 6, dd = n & 63;
                    C[((size_t)h * TWOSPAN + m) * DH + dd] = val;
                } else if (EPI == EPI_SCALE) {
                    C[(size_t)z * SEQ * TWOSPAN + (size_t)m * TWOSPAN + n] = val * alpha;
                } else if (EPI == EPI_SCORE) {
                    const float* c2pz = ex1 + (size_t)z * SEQ * TWOSPAN;
                    int idx1 = g_lut[m - n + 1023];
                    int idx2 = g_lut[n - m + 1023];
                    val = val * alpha + c2pz[(size_t)m * TWOSPAN + idx1]
                                      + p2s[c * 160 + (idx2 - iLo)];
                    C[(size_t)z * SEQ * SEQ + (size_t)m * SEQ + n] = val;
                } else if (EPI == EPI_CTX) {
                    int b = z >> 4, h = z & 15;
                    C[((size_t)b * SEQ + m) * DMODEL + h * DH + n] = val;
                } else { // EPI_OUT
                    val += bias[n] + ex1[(size_t)m * DMODEL + n];
                    C[(size_t)m * DMODEL + n] = val;
                }
            }
        }
        __syncthreads();
    }
}

// ================= softmax & layernorm (SIMT, mem-bound) ====================
__device__ __forceinline__ float block_sum(float v, float* sh) {
    #pragma unroll
    for (int o = 16; o; o >>= 1) v += __shfl_xor_sync(0xffffffffu, v, o);
    int lane = threadIdx.x & 31, w = threadIdx.x >> 5;
    __syncthreads();
    if (lane == 0) sh[w] = v;
    __syncthreads();
    if (w == 0) {
        float x = (lane < (blockDim.x >> 5)) ? sh[lane] : 0.0f;
        #pragma unroll
        for (int o = 16; o; o >>= 1) x += __shfl_xor_sync(0xffffffffu, x, o);
        if (lane == 0) sh[0] = x;
    }
    __syncthreads();
    return sh[0];
}
__device__ __forceinline__ float block_max(float v, float* sh) {
    #pragma unroll
    for (int o = 16; o; o >>= 1) v = fmaxf(v, __shfl_xor_sync(0xffffffffu, v, o));
    int lane = threadIdx.x & 31, w = threadIdx.x >> 5;
    __syncthreads();
    if (lane == 0) sh[w] = v;
    __syncthreads();
    if (w == 0) {
        float x = (lane < (blockDim.x >> 5)) ? sh[lane] : -INFINITY;
        #pragma unroll
        for (int o = 16; o; o >>= 1) x = fmaxf(x, __shfl_xor_sync(0xffffffffu, x, o));
        if (lane == 0) sh[0] = x;
    }
    __syncthreads();
    return sh[0];
}
__global__ void softmax_k(float* __restrict__ Sc, const int* __restrict__ mask) {
    __shared__ float sh[32];
    int row = blockIdx.x;
    int b = row >> 14;
    int i = row & 1023;
    float* p = Sc + (size_t)row * SEQ;
    const int* mrow = mask + ((size_t)b << 20) + ((size_t)i << 10);
    int t = threadIdx.x;
    float4 v = *(const float4*)(p + t * 4);
    int4 mm = *(const int4*)(mrow + t * 4);
    const float NEG = -3.402823466e38f;
    float x0 = mm.x ? v.x : NEG, x1 = mm.y ? v.y : NEG;
    float x2 = mm.z ? v.z : NEG, x3 = mm.w ? v.w : NEG;
    float mx = block_max(fmaxf(fmaxf(x0, x1), fmaxf(x2, x3)), sh);
    float e0 = expf(x0 - mx), e1 = expf(x1 - mx), e2 = expf(x2 - mx), e3 = expf(x3 - mx);
    float s = block_sum(e0 + e1 + e2 + e3, sh);
    float inv = 1.0f / s;
    float4 o;
    o.x = mm.x ? e0 * inv : 0.0f; o.y = mm.y ? e1 * inv : 0.0f;
    o.z = mm.z ? e2 * inv : 0.0f; o.w = mm.w ? e3 * inv : 0.0f;
    *(float4*)(p + t * 4) = o;
}
__global__ void ln_k(float* __restrict__ out, const float* __restrict__ gamma,
                     const float* __restrict__ beta) {
    __shared__ float sh[32];
    int row = blockIdx.x, t = threadIdx.x;
    float* p = out + (size_t)row * DMODEL;
    float4 v = *(const float4*)(p + t * 4);
    float mean = block_sum(v.x + v.y + v.z + v.w, sh) * (1.0f / DMODEL);
    float dx = v.x - mean, dy = v.y - mean, dz = v.z - mean, dw = v.w - mean;
    float var = block_sum(dx*dx + dy*dy + dz*dz + dw*dw, sh) * (1.0f / DMODEL);
    float inv = rsqrtf(var + 1e-7f);
    float4 g = *(const float4*)(gamma + t * 4);
    float4 bb = *(const float4*)(beta + t * 4);
    float4 o;
    o.x = dx*inv*g.x + bb.x; o.y = dy*inv*g.y + bb.y;
    o.z = dz*inv*g.z + bb.z; o.w = dw*inv*g.w + bb.w;
    *(float4*)(p + t * 4) = o;
}

// ================= launch ====================================================
extern "C" void kernel_launch(void* const* d_in, const int* in_sizes, int n_in,
                              void* d_out, int out_size) {
    const float* hidden = (const float*)d_in[0];
    const int*   mask   = (const int*)  d_in[1];
    const float* rel    = (const float*)d_in[2];
    const float* Wq     = (const float*)d_in[3];
    const float* bq     = (const float*)d_in[4];
    const float* Wk     = (const float*)d_in[5];
    const float* bk     = (const float*)d_in[6];
    const float* Wv     = (const float*)d_in[7];
    const float* bv     = (const float*)d_in[8];
    const float* Wo     = (const float*)d_in[9];
    const float* bo     = (const float*)d_in[10];
    const float* gamma  = (const float*)d_in[11];
    const float* beta   = (const float*)d_in[12];
    float* out = (float*)d_out;

    float *q, *k, *vt, *pk, *pq, *c2p, *p2c, *sc, *ctx;
    cudaGetSymbolAddress((void**)&q,   g_q);
    cudaGetSymbolAddress((void**)&k,   g_k);
    cudaGetSymbolAddress((void**)&vt,  g_vt);
    cudaGetSymbolAddress((void**)&pk,  g_posk);
    cudaGetSymbolAddress((void**)&pq,  g_posq);
    cudaGetSymbolAddress((void**)&c2p, g_c2p);
    cudaGetSymbolAddress((void**)&p2c, g_p2c);
    cudaGetSymbolAddress((void**)&sc,  g_sc);
    cudaGetSymbolAddress((void**)&ctx, g_ctx);

    const float alpha = 1.0f / sqrtf((float)(DH * 3));
    const size_t SM128 = (size_t)3 * (128 * 32 + 128 * 32) * 4;   // 98304
    const size_t SM64  = (size_t)3 * (128 * 32 +  64 * 32) * 4;   // 73728

    cudaFuncSetAttribute((const void*)tc_gemm<EPI_HEADS,  128, 32>, cudaFuncAttributeMaxDynamicSharedMemorySize, (int)SM128);
    cudaFuncSetAttribute((const void*)tc_gemm<EPI_HEADS_T,128, 32>, cudaFuncAttributeMaxDynamicSharedMemorySize, (int)SM128);
    cudaFuncSetAttribute((const void*)tc_gemm<EPI_POS,    128, 32>, cudaFuncAttributeMaxDynamicSharedMemorySize, (int)SM128);
    cudaFuncSetAttribute((const void*)tc_gemm<EPI_SCALE,  128,  2>, cudaFuncAttributeMaxDynamicSharedMemorySize, (int)SM128);
    cudaFuncSetAttribute((const void*)tc_gemm<EPI_SCORE,  128,  2>, cudaFuncAttributeMaxDynamicSharedMemorySize, (int)SM128);
    cudaFuncSetAttribute((const void*)tc_gemm<EPI_CTX,     64, 32>, cudaFuncAttributeMaxDynamicSharedMemorySize, (int)SM64);
    cudaFuncSetAttribute((const void*)tc_gemm<EPI_OUT,    128, 32>, cudaFuncAttributeMaxDynamicSharedMemorySize, (int)SM128);

    lut_k<<<2, 1024>>>();

    // Q, K, V projections (M=4096, N=1024, K=1024)
    tc_gemm<EPI_HEADS,  128, 32><<<dim3(8, 32, 1), 256, SM128>>>(hidden, Wq, bq, 0, 0, q,  1024, 0, 0, 0, 1.f);
    tc_gemm<EPI_HEADS,  128, 32><<<dim3(8, 32, 1), 256, SM128>>>(hidden, Wk, bk, 0, 0, k,  1024, 0, 0, 0, 1.f);
    tc_gemm<EPI_HEADS_T,128, 32><<<dim3(8, 32, 1), 256, SM128>>>(hidden, Wv, bv, 0, 0, vt, 1024, 0, 0, 0, 1.f);
    // position projections (M=512)
    tc_gemm<EPI_POS, 128, 32><<<dim3(8, 4, 1), 256, SM128>>>(rel, Wk, bk, 0, 0, pk, 1024, 0, 0, 0, 1.f);
    tc_gemm<EPI_POS, 128, 32><<<dim3(8, 4, 1), 256, SM128>>>(rel, Wq, bq, 0, 0, pq, 1024, 0, 0, 0, 1.f);
    // c2p / p2c attention tables (pre-scaled by alpha), per-z batched, K=64
    tc_gemm<EPI_SCALE, 128, 2><<<dim3(4, 8, NBATCH), 256, SM128>>>(q, pk, 0, 0, 0, c2p, 64, (size_t)SEQ*DH, (size_t)TWOSPAN*DH, NH, alpha);
    tc_gemm<EPI_SCALE, 128, 2><<<dim3(4, 8, NBATCH), 256, SM128>>>(k, pq, 0, 0, 0, p2c, 64, (size_t)SEQ*DH, (size_t)TWOSPAN*DH, NH, alpha);
    // scores = alpha*QK^T + c2p/p2c gathers
    tc_gemm<EPI_SCORE, 128, 2><<<dim3(8, 8, NBATCH), 256, SM128>>>(q, k, 0, c2p, p2c, sc, 64, (size_t)SEQ*DH, (size_t)SEQ*DH, NBATCH, alpha);

    softmax_k<<<NBATCH * SEQ, 256>>>(sc, mask);

    // ctx = P @ V   (A = probs [S,S] K-major, B = vt [64, S] K-major)
    tc_gemm<EPI_CTX, 64, 32><<<dim3(1, 8, NBATCH), 256, SM64>>>(sc, vt, 0, 0, 0, ctx, 1024, (size_t)SEQ*SEQ, (size_t)DH*SEQ, NBATCH, 1.f);
    // output projection + residual
    tc_gemm<EPI_OUT, 128, 32><<<dim3(8, 32, 1), 256, SM128>>>(ctx, Wo, bo, hidden, 0, out, 1024, 0, 0, 0, 1.f);

    ln_k<<<BDIM * SEQ, 256>>>(out, gamma, beta);
}

// round 5
// speedup vs baseline: 3.0041x; 1.7350x over previous
#include <cuda_runtime.h>
#include <math.h>
#include <stdint.h>

#define BDIM 4
#define SEQ 1024
#define DMODEL 1024
#define NH 16
#define DH 64
#define SPAN 256
#define TWOSPAN 512
#define NBATCH (BDIM*NH)   /* 64 */
#define NEGF (-3.402823466e38f)

// ---------------- scratch (device globals; no allocation allowed) ----------
__device__ float g_q   [(size_t)NBATCH * SEQ * DH];        // [z][s][d]
__device__ float g_k   [(size_t)NBATCH * SEQ * DH];        // [z][s][d]
__device__ float g_vt  [(size_t)NBATCH * DH * SEQ];        // [z][d][s]  (transposed V)
__device__ float g_posk[(size_t)NH * TWOSPAN * DH];        // [h][p][d]
__device__ float g_posq[(size_t)NH * TWOSPAN * DH];
__device__ float g_c2p [(size_t)NBATCH * SEQ * TWOSPAN];   // [z][q][p] (pre-scaled)
__device__ float g_p2c [(size_t)NBATCH * SEQ * TWOSPAN];   // [z][k][p] (pre-scaled)
__device__ float g_ctx [(size_t)BDIM * SEQ * DMODEL];
__device__ int   g_lut [2047];                              // clipped bucket idx per delta

// ================= small helpers ============================================
#define MMA_TF32(d, a, b) \
    asm volatile("mma.sync.aligned.m16n8k8.row.col.f32.tf32.tf32.f32 " \
        "{%0,%1,%2,%3}, {%4,%5,%6,%7}, {%8,%9}, {%0,%1,%2,%3};" \
        : "+f"((d)[0]), "+f"((d)[1]), "+f"((d)[2]), "+f"((d)[3]) \
        : "r"((a)[0]), "r"((a)[1]), "r"((a)[2]), "r"((a)[3]), \
          "r"((b)[0]), "r"((b)[1]))

__device__ __forceinline__ void cp16(uint32_t dst, const void* src) {
    asm volatile("cp.async.cg.shared.global [%0], [%1], 16;" :: "r"(dst), "l"(src));
}
#define CP_COMMIT() asm volatile("cp.async.commit_group;" ::: "memory")
#define CP_WAIT(n)  asm volatile("cp.async.wait_group %0;" :: "n"(n) : "memory")

// ================= rel-position bucket LUT ==================================
__device__ __forceinline__ int rel_bucket(int rel) {
    float abs_pos = (rel < 128 && rel > -128) ? 127.0f : fabsf((float)rel);
    if (abs_pos <= 128.0f) return rel;
    float sgn = (rel > 0) ? 1.0f : -1.0f;
    float log_pos = ceilf(logf(abs_pos * (1.0f/128.0f)) / logf(511.0f/128.0f) * 127.0f) + 128.0f;
    return (int)(log_pos * sgn);
}
__global__ void lut_k() {
    int t = blockIdx.x * blockDim.x + threadIdx.x;
    if (t >= 2047) return;
    int b = rel_bucket(t - 1023);
    g_lut[t] = min(max(b + SPAN, 0), TWOSPAN - 1);
}

// ================= unified tf32 mma.sync GEMM (C = A @ B^T + epilogues) =====
#define EPI_HEADS   0
#define EPI_HEADS_T 1
#define EPI_POS     2
#define EPI_SCALE   3
#define EPI_OUT     6

template<int EPI, int BN, int CH>
__global__ void __launch_bounds__(256, 2)
tc_gemm(const float* __restrict__ A, const float* __restrict__ Bm,
        const float* __restrict__ bias, const float* __restrict__ ex1,
        float* __restrict__ C,
        int Ka, size_t sA, size_t sB, int nbMod, float alpha)
{
    constexpr int NS    = 3;
    constexpr int WN    = BN / 4;
    constexpr int NF    = WN / 8;
    constexpr int BNW   = BN / 32;
    constexpr int AELEM = 128 * 32;
    constexpr int BELEM = BN * 32;

    extern __shared__ uint32_t smem_u[];
    const uint32_t smemU = (uint32_t)__cvta_generic_to_shared(smem_u);

    const int tid  = threadIdx.x;
    const int lane = tid & 31, wid = tid >> 5;
    const int wr = wid & 1, wc = wid >> 1;
    const int rq = lane >> 2, cc = lane & 3;
    const int z  = blockIdx.z;
    const int m0 = blockIdx.y * 128;
    const int n0 = blockIdx.x * BN;

    A  += (size_t)z * sA + (size_t)m0 * Ka;
    Bm += (size_t)(nbMod ? (z % nbMod) : 0) * sB + (size_t)n0 * Ka;

    float acc[4][NF][4];
    #pragma unroll
    for (int a = 0; a < 4; a++)
        #pragma unroll
        for (int b = 0; b < NF; b++)
            #pragma unroll
            for (int c = 0; c < 4; c++) acc[a][b][c] = 0.0f;

    int aBase[4][2];
    #pragma unroll
    for (int mi = 0; mi < 4; mi++) {
        int r = wr * 64 + mi * 16 + rq;
        aBase[mi][0] = r * 32 + cc;
        aBase[mi][1] = (r + 8) * 32 + cc;
    }
    int bBase[NF];
    #pragma unroll
    for (int ni = 0; ni < NF; ni++)
        bBase[ni] = (wc * WN + ni * 8 + rq) * 32 + cc;

    const int crow = tid >> 3;
    const int ckg  = tid & 7;

    auto issue = [&](int chunk) {
        const int s  = chunk % NS;
        const int k0 = chunk * 32;
        #pragma unroll
        for (int j = 0; j < 4; j++) {
            int row = j * 32 + crow;
            uint32_t dst = smemU + (uint32_t)(s * AELEM + row * 32 + ((ckg ^ (row & 7)) << 2)) * 4u;
            cp16(dst, A + (size_t)row * Ka + k0 + ckg * 4);
        }
        #pragma unroll
        for (int j = 0; j < BNW; j++) {
            int row = j * 32 + crow;
            uint32_t dst = smemU + (uint32_t)(NS * AELEM + s * BELEM + row * 32 + ((ckg ^ (row & 7)) << 2)) * 4u;
            cp16(dst, Bm + (size_t)row * Ka + k0 + ckg * 4);
        }
    };

    #pragma unroll
    for (int c = 0; c < NS - 1; c++) {
        if (c < CH) issue(c);
        CP_COMMIT();
    }

    #pragma unroll 1
    for (int i = 0; i < CH; i++) {
        CP_WAIT(NS - 2);
        __syncthreads();
        if (i + NS - 1 < CH) issue(i + NS - 1);
        CP_COMMIT();

        const uint32_t* as = smem_u + (i % NS) * AELEM;
        const uint32_t* bs = smem_u + NS * AELEM + (i % NS) * BELEM;
        #pragma unroll
        for (int ks = 0; ks < 4; ks++) {
            const int o0 = ((2 * ks) ^ rq) << 2;
            const int o1 = ((2 * ks + 1) ^ rq) << 2;
            uint32_t af[4][4];
            #pragma unroll
            for (int mi = 0; mi < 4; mi++) {
                af[mi][0] = as[aBase[mi][0] + o0];
                af[mi][1] = as[aBase[mi][1] + o0];
                af[mi][2] = as[aBase[mi][0] + o1];
                af[mi][3] = as[aBase[mi][1] + o1];
            }
            uint32_t bf[NF][2];
            #pragma unroll
            for (int ni = 0; ni < NF; ni++) {
                bf[ni][0] = bs[bBase[ni] + o0];
                bf[ni][1] = bs[bBase[ni] + o1];
            }
            #pragma unroll
            for (int mi = 0; mi < 4; mi++)
                #pragma unroll
                for (int ni = 0; ni < NF; ni++)
                    MMA_TF32(acc[mi][ni], af[mi], bf[ni]);
        }
    }
    CP_WAIT(0);
    __syncthreads();

    // ---------------- epilogue: frags -> smem stage -> global ----------------
    float* stage = (float*)smem_u;

    #pragma unroll 1
    for (int cb = 0; cb < BN / 32; cb++) {
        const int n0c = n0 + cb * 32;
        #pragma unroll
        for (int mi = 0; mi < 4; mi++)
            #pragma unroll
            for (int ni = 0; ni < NF; ni++) {
                int gc = wc * WN + ni * 8 + 2 * cc;
                if ((gc >> 5) == cb) {
                    int sc2 = gc & 31;
                    int r0 = wr * 64 + mi * 16 + rq;
                    stage[r0 * 33 + sc2]           = acc[mi][ni][0];
                    stage[r0 * 33 + sc2 + 1]       = acc[mi][ni][1];
                    stage[(r0 + 8) * 33 + sc2]     = acc[mi][ni][2];
                    stage[(r0 + 8) * 33 + sc2 + 1] = acc[mi][ni][3];
                }
            }
        __syncthreads();

        if (EPI == EPI_HEADS_T) {
            #pragma unroll 1
            for (int j = 0; j < 16; j++) {
                int e = j * 256 + tid;
                int row = e & 127, c = e >> 7;
                int m = m0 + row, n = n0c + c;
                float val = stage[row * 33 + c] + bias[n];
                int b = m >> 10, sq = m & 1023;
                int zz = b * NH + (n >> 6), dd = n & 63;
                C[((size_t)zz * DH + dd) * SEQ + sq] = val;
            }
        } else {
            #pragma unroll 1
            for (int j = 0; j < 16; j++) {
                int e = j * 256 + tid;
                int row = e >> 5, c = e & 31;
                int m = m0 + row, n = n0c + c;
                float val = stage[row * 33 + c];
                if (EPI == EPI_HEADS) {
                    val += bias[n];
                    int b = m >> 10, sq = m & 1023, h = n >> 6, dd = n & 63;
                    C[(((size_t)(b * NH + h)) * SEQ + sq) * DH + dd] = val;
                } else if (EPI == EPI_POS) {
                    val += bias[n];
                    int h = n >> 6, dd = n & 63;
                    C[((size_t)h * TWOSPAN + m) * DH + dd] = val;
                } else if (EPI == EPI_SCALE) {
                    C[(size_t)z * SEQ * TWOSPAN + (size_t)m * TWOSPAN + n] = val * alpha;
                } else { // EPI_OUT
                    val += bias[n] + ex1[(size_t)m * DMODEL + n];
                    C[(size_t)m * DMODEL + n] = val;
                }
            }
        }
        __syncthreads();
    }
}

// ================= flash attention: scores+softmax+PV fused =================
// grid (8 q-tiles, 64 z), 256 threads = 8 warps; warp w owns q rows 16w..16w+15.
// smem (floats): Q 8192 | K 2x4096 | V 2x4096 | P 8192 | lut 2047 ints
__global__ void __launch_bounds__(256, 1)
flash_k(const float* __restrict__ Qg, const float* __restrict__ Kg,
        const float* __restrict__ Vg, const float* __restrict__ c2p,
        const float* __restrict__ p2c, const int* __restrict__ mask,
        float* __restrict__ ctx, float alpha)
{
    constexpr int QS = 0, KS = 8192, VS = 16384, PS = 24576;
    extern __shared__ float fsm[];
    int* lut_s = (int*)&fsm[32768];
    const uint32_t smemU = (uint32_t)__cvta_generic_to_shared(fsm);

    const int tid = threadIdx.x, lane = tid & 31, w = tid >> 5;
    const int rq = lane >> 2, cc = lane & 3;
    const int z = blockIdx.y, m0 = blockIdx.x * 128;
    const int b = z >> 4;

    const float* Qz = Qg + (size_t)z * SEQ * DH;
    const float* Kz = Kg + (size_t)z * SEQ * DH;
    const float* Vz = Vg + (size_t)z * DH * SEQ;
    const float* c2pz = c2p + (size_t)z * SEQ * TWOSPAN;
    const float* p2cz = p2c + (size_t)z * SEQ * TWOSPAN;
    const int* mz = mask + (size_t)b * SEQ * SEQ;

    for (int t = tid; t < 2047; t += 256) lut_s[t] = g_lut[t];

    // Q tile: 128 x 64, split in 2 panels of 32 cols, xor-swizzled
    #pragma unroll
    for (int it = 0; it < 8; it++) {
        int idx = it * 256 + tid;
        int row = idx >> 4, kg = idx & 15;
        int panel = kg >> 3, kg8 = kg & 7;
        uint32_t dst = smemU + (uint32_t)(QS + panel * 4096 + row * 32 + ((kg8 ^ (row & 7)) << 2)) * 4u;
        cp16(dst, Qz + (size_t)(m0 + row) * DH + kg * 4);
    }
    auto issueKV = [&](int t) {
        int s = t & 1, n0 = t * 64;
        #pragma unroll
        for (int it = 0; it < 4; it++) {
            int idx = it * 256 + tid;
            int row = idx >> 4, kg = idx & 15;
            int panel = kg >> 3, kg8 = kg & 7;
            uint32_t sw = (uint32_t)(((kg8 ^ (row & 7)) << 2) + row * 32 + panel * 2048);
            cp16(smemU + (uint32_t)(KS + s * 4096 + sw) * 4u, Kz + (size_t)(n0 + row) * DH + kg * 4);
            cp16(smemU + (uint32_t)(VS + s * 4096 + sw) * 4u, Vz + (size_t)row * SEQ + n0 + kg * 4);
        }
    };
    issueKV(0);
    CP_COMMIT();

    float oacc[8][4];
    #pragma unroll
    for (int f = 0; f < 8; f++)
        #pragma unroll
        for (int e = 0; e < 4; e++) oacc[f][e] = 0.0f;
    float mrow[2] = {NEGF, NEGF};
    float lrow[2] = {0.0f, 0.0f};

    const int iA = m0 + 16 * w + rq, iB = iA + 8;
    const float* c2pA = c2pz + (size_t)iA * TWOSPAN;
    const float* c2pB = c2pz + (size_t)iB * TWOSPAN;
    const int* mA = mz + (size_t)iA * SEQ;
    const int* mB = mz + (size_t)iB * SEQ;

    #pragma unroll 1
    for (int t = 0; t < 16; t++) {
        const int s = t & 1, n0 = t * 64;
        CP_WAIT(0);
        __syncthreads();
        if (t + 1 < 16) issueKV(t + 1);
        CP_COMMIT();

        // ---- S = Q @ K^T ----
        float sacc[8][4];
        #pragma unroll
        for (int f = 0; f < 8; f++)
            #pragma unroll
            for (int e = 0; e < 4; e++) sacc[f][e] = 0.0f;
        #pragma unroll
        for (int ks = 0; ks < 8; ks++) {
            int panel = ks >> 2, kk = ks & 3;
            int o0 = ((2 * kk) ^ rq) << 2, o1 = ((2 * kk + 1) ^ rq) << 2;
            const float* qp = fsm + QS + panel * 4096;
            const float* kp = fsm + KS + s * 4096 + panel * 2048;
            uint32_t af[4];
            af[0] = __float_as_uint(qp[(16 * w + rq) * 32 + cc + o0]);
            af[1] = __float_as_uint(qp[(16 * w + rq + 8) * 32 + cc + o0]);
            af[2] = __float_as_uint(qp[(16 * w + rq) * 32 + cc + o1]);
            af[3] = __float_as_uint(qp[(16 * w + rq + 8) * 32 + cc + o1]);
            #pragma unroll
            for (int f = 0; f < 8; f++) {
                uint32_t bf[2];
                bf[0] = __float_as_uint(kp[(8 * f + rq) * 32 + cc + o0]);
                bf[1] = __float_as_uint(kp[(8 * f + rq) * 32 + cc + o1]);
                MMA_TF32(sacc[f], af, bf);
            }
        }

        // ---- epilogue: scale + c2p + p2c + mask, then online softmax ----
        float mx0 = NEGF, mx1 = NEGF;
        #pragma unroll
        for (int f = 0; f < 8; f++) {
            int j0 = n0 + 8 * f + 2 * cc;
            int2 mm0 = *(const int2*)&mA[j0];
            int2 mm1 = *(const int2*)&mB[j0];
            float v0 = mm0.x ? sacc[f][0] * alpha + c2pA[lut_s[iA - j0 + 1023]]
                               + p2cz[(size_t)j0 * TWOSPAN + lut_s[j0 - iA + 1023]] : NEGF;
            float v1 = mm0.y ? sacc[f][1] * alpha + c2pA[lut_s[iA - j0 + 1022]]
                               + p2cz[(size_t)(j0 + 1) * TWOSPAN + lut_s[j0 + 1 - iA + 1023]] : NEGF;
            float v2 = mm1.x ? sacc[f][2] * alpha + c2pB[lut_s[iB - j0 + 1023]]
                               + p2cz[(size_t)j0 * TWOSPAN + lut_s[j0 - iB + 1023]] : NEGF;
            float v3 = mm1.y ? sacc[f][3] * alpha + c2pB[lut_s[iB - j0 + 1022]]
                               + p2cz[(size_t)(j0 + 1) * TWOSPAN + lut_s[j0 + 1 - iB + 1023]] : NEGF;
            sacc[f][0] = v0; sacc[f][1] = v1; sacc[f][2] = v2; sacc[f][3] = v3;
            mx0 = fmaxf(mx0, fmaxf(v0, v1));
            mx1 = fmaxf(mx1, fmaxf(v2, v3));
        }
        mx0 = fmaxf(mx0, __shfl_xor_sync(0xffffffffu, mx0, 1));
        mx0 = fmaxf(mx0, __shfl_xor_sync(0xffffffffu, mx0, 2));
        mx1 = fmaxf(mx1, __shfl_xor_sync(0xffffffffu, mx1, 1));
        mx1 = fmaxf(mx1, __shfl_xor_sync(0xffffffffu, mx1, 2));
        float mn0 = fmaxf(mrow[0], mx0), mn1 = fmaxf(mrow[1], mx1);
        float sc0 = __expf(mrow[0] - mn0), sc1 = __expf(mrow[1] - mn1);
        mrow[0] = mn0; mrow[1] = mn1;

        float rs0 = 0.0f, rs1 = 0.0f;
        const int lrA = 16 * w + rq, lrB = lrA + 8;
        #pragma unroll
        for (int f = 0; f < 8; f++) {
            float e0 = __expf(sacc[f][0] - mn0);
            float e1 = __expf(sacc[f][1] - mn0);
            float e2 = __expf(sacc[f][2] - mn1);
            float e3 = __expf(sacc[f][3] - mn1);
            rs0 += e0 + e1; rs1 += e2 + e3;
            // masked entries contribute to denominator (matching reference) but 0 to PV
            float p0 = (sacc[f][0] == NEGF) ? 0.0f : e0;
            float p1 = (sacc[f][1] == NEGF) ? 0.0f : e1;
            float p2 = (sacc[f][2] == NEGF) ? 0.0f : e2;
            float p3 = (sacc[f][3] == NEGF) ? 0.0f : e3;
            int jl = 8 * f + 2 * cc;
            int panel = f >> 2, col32 = jl & 31;
            int base = PS + panel * 4096;
            int kgrp = col32 >> 2, rem = col32 & 3;
            fsm[base + lrA * 32 + ((kgrp ^ (lrA & 7)) << 2) + rem]     = p0;
            fsm[base + lrA * 32 + (((col32 + 1) >> 2 ^ (lrA & 7)) << 2) + ((col32 + 1) & 3)] = p1;
            fsm[base + lrB * 32 + ((kgrp ^ (lrB & 7)) << 2) + rem]     = p2;
            fsm[base + lrB * 32 + (((col32 + 1) >> 2 ^ (lrB & 7)) << 2) + ((col32 + 1) & 3)] = p3;
        }
        rs0 += __shfl_xor_sync(0xffffffffu, rs0, 1);
        rs0 += __shfl_xor_sync(0xffffffffu, rs0, 2);
        rs1 += __shfl_xor_sync(0xffffffffu, rs1, 1);
        rs1 += __shfl_xor_sync(0xffffffffu, rs1, 2);
        lrow[0] = lrow[0] * sc0 + rs0;
        lrow[1] = lrow[1] * sc1 + rs1;
        #pragma unroll
        for (int f = 0; f < 8; f++) {
            oacc[f][0] *= sc0; oacc[f][1] *= sc0;
            oacc[f][2] *= sc1; oacc[f][3] *= sc1;
        }
        __syncthreads();

        // ---- O += P @ V^T ----
        #pragma unroll
        for (int ks = 0; ks < 8; ks++) {
            int panel = ks >> 2, kk = ks & 3;
            int o0 = ((2 * kk) ^ rq) << 2, o1 = ((2 * kk + 1) ^ rq) << 2;
            const float* pp = fsm + PS + panel * 4096;
            const float* vp = fsm + VS + s * 4096 + panel * 2048;
            uint32_t af[4];
            af[0] = __float_as_uint(pp[(16 * w + rq) * 32 + cc + o0]);
            af[1] = __float_as_uint(pp[(16 * w + rq + 8) * 32 + cc + o0]);
            af[2] = __float_as_uint(pp[(16 * w + rq) * 32 + cc + o1]);
            af[3] = __float_as_uint(pp[(16 * w + rq + 8) * 32 + cc + o1]);
            #pragma unroll
            for (int f = 0; f < 8; f++) {
                uint32_t bf[2];
                bf[0] = __float_as_uint(vp[(8 * f + rq) * 32 + cc + o0]);
                bf[1] = __float_as_uint(vp[(8 * f + rq) * 32 + cc + o1]);
                MMA_TF32(oacc[f], af, bf);
            }
        }
    }

    // ---- write ctx: [b][s][h*64+d] ----
    float inv0 = 1.0f / lrow[0], inv1 = 1.0f / lrow[1];
    int h = z & 15;
    float* crow0 = ctx + ((size_t)b * SEQ + (size_t)(m0 + 16 * w + rq)) * DMODEL + h * DH;
    float* crow1 = crow0 + (size_t)8 * DMODEL;
    #pragma unroll
    for (int f = 0; f < 8; f++) {
        int d0 = 8 * f + 2 * cc;
        float2 a = make_float2(oacc[f][0] * inv0, oacc[f][1] * inv0);
        float2 c = make_float2(oacc[f][2] * inv1, oacc[f][3] * inv1);
        *(float2*)&crow0[d0] = a;
        *(float2*)&crow1[d0] = c;
    }
}

// ================= layernorm ================================================
__device__ __forceinline__ float block_sum(float v, float* sh) {
    #pragma unroll
    for (int o = 16; o; o >>= 1) v += __shfl_xor_sync(0xffffffffu, v, o);
    int lane = threadIdx.x & 31, w = threadIdx.x >> 5;
    __syncthreads();
    if (lane == 0) sh[w] = v;
    __syncthreads();
    if (w == 0) {
        float x = (lane < (blockDim.x >> 5)) ? sh[lane] : 0.0f;
        #pragma unroll
        for (int o = 16; o; o >>= 1) x += __shfl_xor_sync(0xffffffffu, x, o);
        if (lane == 0) sh[0] = x;
    }
    __syncthreads();
    return sh[0];
}
__global__ void ln_k(float* __restrict__ out, const float* __restrict__ gamma,
                     const float* __restrict__ beta) {
    __shared__ float sh[32];
    int row = blockIdx.x, t = threadIdx.x;
    float* p = out + (size_t)row * DMODEL;
    float4 v = *(const float4*)(p + t * 4);
    float mean = block_sum(v.x + v.y + v.z + v.w, sh) * (1.0f / DMODEL);
    float dx = v.x - mean, dy = v.y - mean, dz = v.z - mean, dw = v.w - mean;
    float var = block_sum(dx*dx + dy*dy + dz*dz + dw*dw, sh) * (1.0f / DMODEL);
    float inv = rsqrtf(var + 1e-7f);
    float4 g = *(const float4*)(gamma + t * 4);
    float4 bb = *(const float4*)(beta + t * 4);
    float4 o;
    o.x = dx*inv*g.x + bb.x; o.y = dy*inv*g.y + bb.y;
    o.z = dz*inv*g.z + bb.z; o.w = dw*inv*g.w + bb.w;
    *(float4*)(p + t * 4) = o;
}

// ================= launch ====================================================
extern "C" void kernel_launch(void* const* d_in, const int* in_sizes, int n_in,
                              void* d_out, int out_size) {
    const float* hidden = (const float*)d_in[0];
    const int*   mask   = (const int*)  d_in[1];
    const float* rel    = (const float*)d_in[2];
    const float* Wq     = (const float*)d_in[3];
    const float* bq     = (const float*)d_in[4];
    const float* Wk     = (const float*)d_in[5];
    const float* bk     = (const float*)d_in[6];
    const float* Wv     = (const float*)d_in[7];
    const float* bv     = (const float*)d_in[8];
    const float* Wo     = (const float*)d_in[9];
    const float* bo     = (const float*)d_in[10];
    const float* gamma  = (const float*)d_in[11];
    const float* beta   = (const float*)d_in[12];
    float* out = (float*)d_out;

    float *q, *k, *vt, *pk, *pq, *c2p, *p2c, *ctx;
    cudaGetSymbolAddress((void**)&q,   g_q);
    cudaGetSymbolAddress((void**)&k,   g_k);
    cudaGetSymbolAddress((void**)&vt,  g_vt);
    cudaGetSymbolAddress((void**)&pk,  g_posk);
    cudaGetSymbolAddress((void**)&pq,  g_posq);
    cudaGetSymbolAddress((void**)&c2p, g_c2p);
    cudaGetSymbolAddress((void**)&p2c, g_p2c);
    cudaGetSymbolAddress((void**)&ctx, g_ctx);

    const float alpha = 1.0f / sqrtf((float)(DH * 3));
    const size_t SM128 = (size_t)3 * (128 * 32 + 128 * 32) * 4;   // 98304
    const size_t SMF   = (size_t)32768 * 4 + 2048 * 4;            // 139264

    cudaFuncSetAttribute((const void*)tc_gemm<EPI_HEADS,  128, 32>, cudaFuncAttributeMaxDynamicSharedMemorySize, (int)SM128);
    cudaFuncSetAttribute((const void*)tc_gemm<EPI_HEADS_T,128, 32>, cudaFuncAttributeMaxDynamicSharedMemorySize, (int)SM128);
    cudaFuncSetAttribute((const void*)tc_gemm<EPI_POS,    128, 32>, cudaFuncAttributeMaxDynamicSharedMemorySize, (int)SM128);
    cudaFuncSetAttribute((const void*)tc_gemm<EPI_SCALE,  128,  2>, cudaFuncAttributeMaxDynamicSharedMemorySize, (int)SM128);
    cudaFuncSetAttribute((const void*)tc_gemm<EPI_OUT,    128, 32>, cudaFuncAttributeMaxDynamicSharedMemorySize, (int)SM128);
    cudaFuncSetAttribute((const void*)flash_k, cudaFuncAttributeMaxDynamicSharedMemorySize, (int)SMF);

    lut_k<<<2, 1024>>>();

    // Q, K, V projections (M=4096, N=1024, K=1024)
    tc_gemm<EPI_HEADS,  128, 32><<<dim3(8, 32, 1), 256, SM128>>>(hidden, Wq, bq, 0, q,  1024, 0, 0, 0, 1.f);
    tc_gemm<EPI_HEADS,  128, 32><<<dim3(8, 32, 1), 256, SM128>>>(hidden, Wk, bk, 0, k,  1024, 0, 0, 0, 1.f);
    tc_gemm<EPI_HEADS_T,128, 32><<<dim3(8, 32, 1), 256, SM128>>>(hidden, Wv, bv, 0, vt, 1024, 0, 0, 0, 1.f);
    // position projections (M=512)
    tc_gemm<EPI_POS, 128, 32><<<dim3(8, 4, 1), 256, SM128>>>(rel, Wk, bk, 0, pk, 1024, 0, 0, 0, 1.f);
    tc_gemm<EPI_POS, 128, 32><<<dim3(8, 4, 1), 256, SM128>>>(rel, Wq, bq, 0, pq, 1024, 0, 0, 0, 1.f);
    // c2p / p2c attention tables (pre-scaled by alpha), per-z batched, K=64
    tc_gemm<EPI_SCALE, 128, 2><<<dim3(4, 8, NBATCH), 256, SM128>>>(q, pk, 0, 0, c2p, 64, (size_t)SEQ*DH, (size_t)TWOSPAN*DH, NH, alpha);
    tc_gemm<EPI_SCALE, 128, 2><<<dim3(4, 8, NBATCH), 256, SM128>>>(k, pq, 0, 0, p2c, 64, (size_t)SEQ*DH, (size_t)TWOSPAN*DH, NH, alpha);

    // fused attention: scores + masked softmax + P@V
    flash_k<<<dim3(8, NBATCH), 256, SMF>>>(q, k, vt, c2p, p2c, mask, ctx, alpha);

    // output projection + residual
    tc_gemm<EPI_OUT, 128, 32><<<dim3(8, 32, 1), 256, SM128>>>(ctx, Wo, bo, hidden, out, 1024, 0, 0, 0, 1.f);

    ln_k<<<BDIM * SEQ, 256>>>(out, gamma, beta);
}